// round 1
// baseline (speedup 1.0000x reference)
#include <cuda_runtime.h>
#include <cuda_bf16.h>
#include <cstdint>

// ============================================================================
// QuantizedLinear: y[M,N] = (x[M,K] @ W_int8[N,K]^T) * (1/127)
//   M = 8192 (4*2048), N = 4096, K = 4096
//
// Strategy:
//   - W int8 values (0..126) are EXACT in bf16. Keep integer-valued bf16 W,
//     apply 1/127 scale in fp32 epilogue (avoids bf16-rounding the scale).
//   - x split: x = hi + lo, hi = bf16(x), lo = bf16(x - hi). Two bf16 MMAs
//     sharing B fragments and one fp32 accumulator -> ~1e-5 rel err.
//   - mma.sync.m16n8k16 bf16, 128x128x32 CTA tile, 8 warps (2x4),
//     3-stage cp.async pipeline, padded smem rows (40 bf16 = 80B stride,
//     conflict-free for ldmatrix / LDS.32 / STS.128 phases).
// ============================================================================

#define KDIM   4096
#define NDIM   4096
#define BM     128
#define BN     128
#define BK     32
#define STAGES 3
#define PADK   40                      // smem row stride in bf16 elements
#define TILE_BYTES (BM * PADK * 2)     // 10240 B per tile (aHi / aLo / B)
#define STAGE_BYTES (3 * TILE_BYTES)   // 30720 B
#define SMEM_BYTES (STAGES * STAGE_BYTES)  // 92160 B

#define SCALE (1.0f / 127.0f)

// Scratch (device globals: allocation-free per harness rules)
__device__ __nv_bfloat16 g_W[(size_t)NDIM * KDIM];        // 32 MB
__device__ __nv_bfloat16 g_Ahi[(size_t)8192 * KDIM];      // 64 MB
__device__ __nv_bfloat16 g_Alo[(size_t)8192 * KDIM];      // 64 MB

// ---------------------------------------------------------------------------
// Prep kernels
// ---------------------------------------------------------------------------
__global__ void k_convw(const int4* __restrict__ w, __nv_bfloat16* __restrict__ o, int n4) {
    int i = blockIdx.x * blockDim.x + threadIdx.x;
    if (i >= n4) return;
    int4 v = w[i];
    __nv_bfloat162 p0, p1;
    p0.x = __float2bfloat16_rn((float)v.x);
    p0.y = __float2bfloat16_rn((float)v.y);
    p1.x = __float2bfloat16_rn((float)v.z);
    p1.y = __float2bfloat16_rn((float)v.w);
    __nv_bfloat162* o2 = reinterpret_cast<__nv_bfloat162*>(o);
    o2[2 * i]     = p0;
    o2[2 * i + 1] = p1;
}

__global__ void k_split(const float4* __restrict__ x,
                        __nv_bfloat16* __restrict__ hi,
                        __nv_bfloat16* __restrict__ lo, int n4) {
    int i = blockIdx.x * blockDim.x + threadIdx.x;
    if (i >= n4) return;
    float4 v = x[i];
    __nv_bfloat162 h0, h1, l0, l1;
    h0.x = __float2bfloat16_rn(v.x);
    h0.y = __float2bfloat16_rn(v.y);
    h1.x = __float2bfloat16_rn(v.z);
    h1.y = __float2bfloat16_rn(v.w);
    l0.x = __float2bfloat16_rn(v.x - __bfloat162float(h0.x));
    l0.y = __float2bfloat16_rn(v.y - __bfloat162float(h0.y));
    l1.x = __float2bfloat16_rn(v.z - __bfloat162float(h1.x));
    l1.y = __float2bfloat16_rn(v.w - __bfloat162float(h1.y));
    __nv_bfloat162* h2 = reinterpret_cast<__nv_bfloat162*>(hi);
    __nv_bfloat162* l2 = reinterpret_cast<__nv_bfloat162*>(lo);
    h2[2 * i] = h0; h2[2 * i + 1] = h1;
    l2[2 * i] = l0; l2[2 * i + 1] = l1;
}

// ---------------------------------------------------------------------------
// PTX helpers
// ---------------------------------------------------------------------------
__device__ __forceinline__ void cp_async16(uint32_t saddr, const void* gaddr) {
    asm volatile("cp.async.cg.shared.global [%0], [%1], 16;\n" :: "r"(saddr), "l"(gaddr));
}
__device__ __forceinline__ void cp_commit() {
    asm volatile("cp.async.commit_group;\n" ::: "memory");
}
template <int N>
__device__ __forceinline__ void cp_wait() {
    asm volatile("cp.async.wait_group %0;\n" :: "n"(N) : "memory");
}
__device__ __forceinline__ void ldmatrix_x4(uint32_t& r0, uint32_t& r1, uint32_t& r2, uint32_t& r3,
                                            uint32_t saddr) {
    asm volatile("ldmatrix.sync.aligned.m8n8.x4.shared.b16 {%0,%1,%2,%3}, [%4];"
                 : "=r"(r0), "=r"(r1), "=r"(r2), "=r"(r3) : "r"(saddr));
}
__device__ __forceinline__ uint32_t lds32(uint32_t saddr) {
    uint32_t v;
    asm volatile("ld.shared.b32 %0, [%1];" : "=r"(v) : "r"(saddr));
    return v;
}
__device__ __forceinline__ void mma16816(float* c, const uint32_t* a, const uint32_t* b) {
    asm volatile(
        "mma.sync.aligned.m16n8k16.row.col.f32.bf16.bf16.f32 "
        "{%0,%1,%2,%3}, {%4,%5,%6,%7}, {%8,%9}, {%0,%1,%2,%3};"
        : "+f"(c[0]), "+f"(c[1]), "+f"(c[2]), "+f"(c[3])
        : "r"(a[0]), "r"(a[1]), "r"(a[2]), "r"(a[3]), "r"(b[0]), "r"(b[1]));
}

// ---------------------------------------------------------------------------
// GEMM kernel
// ---------------------------------------------------------------------------
__global__ __launch_bounds__(256, 2)
void gemm_kernel(const __nv_bfloat16* __restrict__ Ahi,
                 const __nv_bfloat16* __restrict__ Alo,
                 const __nv_bfloat16* __restrict__ Bw,
                 float* __restrict__ C, int M) {
    extern __shared__ __nv_bfloat16 smem[];
    const uint32_t smem_u32 = (uint32_t)__cvta_generic_to_shared(smem);

    const int tid  = threadIdx.x;
    const int lane = tid & 31;
    const int warp = tid >> 5;
    const int warp_m = warp >> 2;   // 0..1 -> 64 rows each
    const int warp_n = warp & 3;    // 0..3 -> 32 cols each

    const int bm = blockIdx.y * BM;
    const int bn = blockIdx.x * BN;

    // load mapping: thread t handles row (t&127), 16B chunks (t>>7) and (t>>7)+2
    const int lrow   = tid & 127;
    const int lchunk = tid >> 7;

    const size_t gaRowBase = (size_t)(bm + lrow) * KDIM;  // elem offset (A rows)
    const size_t gbRowBase = (size_t)(bn + lrow) * KDIM;  // elem offset (W rows)
    const uint32_t sRowBase = lrow * (PADK * 2);          // byte offset within tile

    auto issue_stage = [&](int kt, int s) {
        const int k0 = kt * BK;
        const uint32_t sb = smem_u32 + s * STAGE_BYTES + sRowBase;
        #pragma unroll
        for (int cc = 0; cc < 2; cc++) {
            const int c = lchunk + 2 * cc;             // 0..3, 16B chunks
            const size_t ge = (size_t)k0 + c * 8;      // elem offset in row
            cp_async16(sb + c * 16,                   Ahi + gaRowBase + ge);
            cp_async16(sb + TILE_BYTES + c * 16,      Alo + gaRowBase + ge);
            cp_async16(sb + 2 * TILE_BYTES + c * 16,  Bw  + gbRowBase + ge);
        }
    };

    float acc[4][4][4];
    #pragma unroll
    for (int mi = 0; mi < 4; mi++)
        #pragma unroll
        for (int ni = 0; ni < 4; ni++)
            #pragma unroll
            for (int r = 0; r < 4; r++) acc[mi][ni][r] = 0.0f;

    const int KT = KDIM / BK;  // 128

    // prologue: stages 0, 1
    issue_stage(0, 0); cp_commit();
    issue_stage(1, 1); cp_commit();

    // precomputed fragment addressing (byte offsets within a tile)
    const uint32_t aRow  = (uint32_t)(warp_m * 64 + (lane & 15)) * (PADK * 2) + (lane >> 4) * 16;
    const uint32_t bRowB = (uint32_t)(warp_n * 32 + (lane >> 2)) * (PADK * 2) + (lane & 3) * 4;

    for (int kt = 0; kt < KT; kt++) {
        cp_wait<1>();
        __syncthreads();

        if (kt + 2 < KT) issue_stage(kt + 2, (kt + 2) % STAGES);
        cp_commit();  // always commit (keeps pending-group count uniform)

        const uint32_t sBase = smem_u32 + (kt % STAGES) * STAGE_BYTES;
        const uint32_t sHi = sBase;
        const uint32_t sLo = sBase + TILE_BYTES;
        const uint32_t sB  = sBase + 2 * TILE_BYTES;

        #pragma unroll
        for (int ks = 0; ks < BK; ks += 16) {
            // B fragments (shared by hi and lo passes)
            uint32_t bfr[4][2];
            #pragma unroll
            for (int ni = 0; ni < 4; ni++) {
                const uint32_t ba = sB + bRowB + ni * 8 * (PADK * 2) + ks * 2;
                bfr[ni][0] = lds32(ba);
                bfr[ni][1] = lds32(ba + 16);
            }
            // hi pass
            uint32_t afr[4][4];
            #pragma unroll
            for (int mi = 0; mi < 4; mi++)
                ldmatrix_x4(afr[mi][0], afr[mi][1], afr[mi][2], afr[mi][3],
                            sHi + aRow + mi * 16 * (PADK * 2) + ks * 2);
            #pragma unroll
            for (int mi = 0; mi < 4; mi++)
                #pragma unroll
                for (int ni = 0; ni < 4; ni++)
                    mma16816(acc[mi][ni], afr[mi], bfr[ni]);
            // lo pass (reuse B fragments)
            #pragma unroll
            for (int mi = 0; mi < 4; mi++)
                ldmatrix_x4(afr[mi][0], afr[mi][1], afr[mi][2], afr[mi][3],
                            sLo + aRow + mi * 16 * (PADK * 2) + ks * 2);
            #pragma unroll
            for (int mi = 0; mi < 4; mi++)
                #pragma unroll
                for (int ni = 0; ni < 4; ni++)
                    mma16816(acc[mi][ni], afr[mi], bfr[ni]);
        }
        __syncthreads();
    }

    // epilogue: c0,c1 -> row (lane>>2), cols 2*(lane&3)+{0,1}; c2,c3 -> row+8
    const int erow = bm + warp_m * 64 + (lane >> 2);
    const int ecol = bn + warp_n * 32 + 2 * (lane & 3);
    #pragma unroll
    for (int mi = 0; mi < 4; mi++) {
        #pragma unroll
        for (int ni = 0; ni < 4; ni++) {
            const int r0 = erow + mi * 16;
            const int cc = ecol + ni * 8;
            float2 v01 = make_float2(acc[mi][ni][0] * SCALE, acc[mi][ni][1] * SCALE);
            float2 v23 = make_float2(acc[mi][ni][2] * SCALE, acc[mi][ni][3] * SCALE);
            *reinterpret_cast<float2*>(C + (size_t)r0 * NDIM + cc)       = v01;
            *reinterpret_cast<float2*>(C + (size_t)(r0 + 8) * NDIM + cc) = v23;
        }
    }
}

// ---------------------------------------------------------------------------
// kernel_launch
// ---------------------------------------------------------------------------
extern "C" void kernel_launch(void* const* d_in, const int* in_sizes, int n_in,
                              void* d_out, int out_size) {
    const float* x = (const float*)d_in[0];
    const int*   w = (const int*)d_in[1];
    float* out = (float*)d_out;

    const int M = in_sizes[0] / KDIM;  // 8192

    void *pW, *pHi, *pLo;
    cudaGetSymbolAddress(&pW,  g_W);
    cudaGetSymbolAddress(&pHi, g_Ahi);
    cudaGetSymbolAddress(&pLo, g_Alo);

    const int n4w = (NDIM * KDIM) / 4;
    k_convw<<<(n4w + 255) / 256, 256>>>((const int4*)w, (__nv_bfloat16*)pW, n4w);

    const int n4x = in_sizes[0] / 4;
    k_split<<<(n4x + 255) / 256, 256>>>((const float4*)x, (__nv_bfloat16*)pHi,
                                        (__nv_bfloat16*)pLo, n4x);

    cudaFuncSetAttribute(gemm_kernel, cudaFuncAttributeMaxDynamicSharedMemorySize, SMEM_BYTES);
    dim3 grid(NDIM / BN, M / BM);
    gemm_kernel<<<grid, 256, SMEM_BYTES>>>((const __nv_bfloat16*)pHi,
                                           (const __nv_bfloat16*)pLo,
                                           (const __nv_bfloat16*)pW, out, M);
}

// round 3
// speedup vs baseline: 2.4686x; 2.4686x over previous
#include <cuda_runtime.h>
#include <cuda_fp16.h>
#include <cstdint>

// ============================================================================
// QuantizedLinear: y[M,N] = (x[M,K] @ W_int8[N,K]^T) / 127
//   M=8192, N=4096, K=4096.  sm_103 legacy tensor path (tcgen05 blocked by
//   toolchain target), so: minimize HMMA count.
//
//   - fp16 single pass: W (0..126) exact in fp16; x->fp16 RN gives ~1.4e-4
//     normwise output error (fp32 accumulate, 1/127 applied in fp32 epilogue).
//   - Prep kernel pre-swizzles (SW128-style) fp16 tiles in gmem so the GEMM
//     loads each stage with plain cp.async.bulk + mbarrier (compiles on
//     sm_103), 4-stage ring, dedicated producer warp, no mainloop barriers.
//   - CTA tile 128x256, BK=64, 8 compute warps (2x4, warp tile 64x64),
//     mma.sync.m16n8k16.f32.f16.f16.f32.
// ============================================================================

#define KDIM 4096
#define NDIM 4096
#define MDIM 8192
#define BM   128
#define BN   256
#define BK   64
#define NKT  (KDIM / BK)          // 64
#define STAGES 4

#define A_TILE_BYTES (BM * BK * 2)                  // 16384
#define B_TILE_BYTES (BN * BK * 2)                  // 32768
#define STAGE_BYTES  (A_TILE_BYTES + B_TILE_BYTES)  // 49152
#define TILES_OFF    1024
#define SMEM_BYTES   (TILES_OFF + STAGES * STAGE_BYTES)  // 197632

#define SCALE (1.0f / 127.0f)

// pre-swizzled fp16 tile scratch (device globals: allocation-free)
__device__ __half g_W[(size_t)NDIM * KDIM];   // 32 MB, tiles [nt][kt][256x64]
__device__ __half g_A[(size_t)MDIM * KDIM];   // 64 MB, tiles [mt][kt][128x64]

__host__ __device__ __forceinline__ uint32_t swz128(uint32_t off) {
    return off ^ ((off >> 3) & 0x70);
}

__device__ __forceinline__ uint32_t pack_h2(float a, float b) {
    __half2 t;
    t.x = __float2half_rn(a);
    t.y = __float2half_rn(b);
    return *reinterpret_cast<uint32_t*>(&t);
}

// ---------------------------------------------------------------------------
// Merged prep: W int32 -> fp16 tiles, x fp32 -> fp16 tiles (SW128 pre-applied)
// One launch -> gemm is every 2nd launch (ncu -s 5 -c 1 lands on gemm).
// ---------------------------------------------------------------------------
#define W_CHUNKS (NDIM * (KDIM / 8))   // 2097152
#define X_CHUNKS (MDIM * (KDIM / 8))   // 4194304

__global__ void k_prep(const int4* __restrict__ w, const float4* __restrict__ x,
                       uint4* __restrict__ Wt, uint4* __restrict__ At) {
    uint32_t t = blockIdx.x * blockDim.x + threadIdx.x;
    if (t < W_CHUNKS) {
        uint32_t n = t >> 9, cg = t & 511;           // 8-elem chunk along K
        int4 v0 = w[(size_t)n * 1024 + cg * 2];
        int4 v1 = w[(size_t)n * 1024 + cg * 2 + 1];
        uint4 o;
        o.x = pack_h2((float)v0.x, (float)v0.y);
        o.y = pack_h2((float)v0.z, (float)v0.w);
        o.z = pack_h2((float)v1.x, (float)v1.y);
        o.w = pack_h2((float)v1.z, (float)v1.w);
        uint32_t nt = n >> 8, r = n & 255, kt = cg >> 3, c = cg & 7;
        size_t tile_u4 = ((size_t)nt * NKT + kt) * (B_TILE_BYTES / 16);
        Wt[tile_u4 + (swz128(r * 128 + c * 16) >> 4)] = o;
    } else {
        t -= W_CHUNKS;
        uint32_t m = t >> 9, cg = t & 511;
        float4 v0 = x[(size_t)m * 1024 + cg * 2];
        float4 v1 = x[(size_t)m * 1024 + cg * 2 + 1];
        uint4 o;
        o.x = pack_h2(v0.x, v0.y);
        o.y = pack_h2(v0.z, v0.w);
        o.z = pack_h2(v1.x, v1.y);
        o.w = pack_h2(v1.z, v1.w);
        uint32_t mt = m >> 7, r = m & 127, kt = cg >> 3, c = cg & 7;
        size_t tile_u4 = ((size_t)mt * NKT + kt) * (A_TILE_BYTES / 16);
        At[tile_u4 + (swz128(r * 128 + c * 16) >> 4)] = o;
    }
}

// ---------------------------------------------------------------------------
// PTX helpers (all verified to compile on sm_103 target)
// ---------------------------------------------------------------------------
__device__ __forceinline__ bool elect_one() {
    uint32_t pred;
    asm volatile("{\n\t.reg .pred p;\n\telect.sync _|p, 0xFFFFFFFF;\n\t"
                 "selp.b32 %0, 1, 0, p;\n\t}" : "=r"(pred));
    return pred != 0;
}
__device__ __forceinline__ void mbar_init(uint32_t a, uint32_t cnt) {
    asm volatile("mbarrier.init.shared.b64 [%0], %1;" :: "r"(a), "r"(cnt) : "memory");
}
__device__ __forceinline__ void mbar_expect_tx(uint32_t a, uint32_t bytes) {
    asm volatile("mbarrier.arrive.expect_tx.shared.b64 _, [%0], %1;"
                 :: "r"(a), "r"(bytes) : "memory");
}
__device__ __forceinline__ void mbar_arrive(uint32_t a) {
    asm volatile("mbarrier.arrive.shared.b64 _, [%0];" :: "r"(a) : "memory");
}
__device__ __forceinline__ void mbar_wait(uint32_t a, uint32_t parity) {
    asm volatile(
        "{\n\t.reg .pred P1;\n"
        "WAIT_LOOP_%=:\n\t"
        "mbarrier.try_wait.parity.acquire.cta.shared::cta.b64 P1, [%0], %1, 0x989680;\n\t"
        "@P1 bra.uni WAIT_DONE_%=;\n\t"
        "bra.uni WAIT_LOOP_%=;\n"
        "WAIT_DONE_%=:\n\t}"
        :: "r"(a), "r"(parity) : "memory");
}
__device__ __forceinline__ void bulk_g2s(uint32_t dst, const void* src,
                                         uint32_t bytes, uint32_t mbar) {
    asm volatile(
        "cp.async.bulk.shared::cluster.global.mbarrier::complete_tx::bytes "
        "[%0], [%1], %2, [%3];"
        :: "r"(dst), "l"(src), "r"(bytes), "r"(mbar) : "memory");
}
__device__ __forceinline__ void ldmatrix_x4(uint32_t& r0, uint32_t& r1,
                                            uint32_t& r2, uint32_t& r3, uint32_t a) {
    asm volatile("ldmatrix.sync.aligned.m8n8.x4.shared.b16 {%0,%1,%2,%3}, [%4];"
                 : "=r"(r0), "=r"(r1), "=r"(r2), "=r"(r3) : "r"(a));
}
__device__ __forceinline__ uint32_t lds32(uint32_t a) {
    uint32_t v;
    asm volatile("ld.shared.b32 %0, [%1];" : "=r"(v) : "r"(a));
    return v;
}
__device__ __forceinline__ void mma16816(float* c, const uint32_t* a, const uint32_t* b) {
    asm volatile(
        "mma.sync.aligned.m16n8k16.row.col.f32.f16.f16.f32 "
        "{%0,%1,%2,%3}, {%4,%5,%6,%7}, {%8,%9}, {%0,%1,%2,%3};"
        : "+f"(c[0]), "+f"(c[1]), "+f"(c[2]), "+f"(c[3])
        : "r"(a[0]), "r"(a[1]), "r"(a[2]), "r"(a[3]), "r"(b[0]), "r"(b[1]));
}

// ---------------------------------------------------------------------------
// GEMM: 288 threads. Warps 0-7 compute (2x4, 64x64 tiles). Warp 8: producer.
// ---------------------------------------------------------------------------
__global__ __launch_bounds__(288, 1)
void gemm_kernel(float* __restrict__ C) {
    extern __shared__ char smem[];
    const uint32_t sb = (uint32_t)__cvta_generic_to_shared(smem);
    const int tid  = threadIdx.x;
    const int warp = tid >> 5;
    const int lane = tid & 31;
    const int nt = blockIdx.x;   // 0..15
    const int mt = blockIdx.y;   // 0..63

    const uint32_t mb_full  = sb;        // 4 x 8B
    const uint32_t mb_empty = sb + 32;   // 4 x 8B

    if (tid == 0) {
        #pragma unroll
        for (int s = 0; s < STAGES; s++) {
            mbar_init(mb_full  + 8 * s, 1);    // tx-based completion
            mbar_init(mb_empty + 8 * s, 256);  // all compute threads arrive
        }
    }
    __syncthreads();

    if (warp == 8) {
        // ---------------- producer ----------------
        if (elect_one()) {
            const char* pA = (const char*)g_A + (size_t)mt * NKT * A_TILE_BYTES;
            const char* pB = (const char*)g_W + (size_t)nt * NKT * B_TILE_BYTES;
            for (int j = 0; j < NKT; j++) {
                const int s = j & 3;
                mbar_wait(mb_empty + 8 * s, ((j >> 2) + 1) & 1);  // 1st pass free
                const uint32_t st = sb + TILES_OFF + s * STAGE_BYTES;
                mbar_expect_tx(mb_full + 8 * s, STAGE_BYTES);
                bulk_g2s(st, pA + (size_t)j * A_TILE_BYTES, A_TILE_BYTES,
                         mb_full + 8 * s);
                bulk_g2s(st + A_TILE_BYTES, pB + (size_t)j * B_TILE_BYTES,
                         B_TILE_BYTES, mb_full + 8 * s);
            }
        }
        return;
    }

    // ---------------- compute warps ----------------
    const int warp_m = warp >> 2;   // 0..1 -> 64 rows
    const int warp_n = warp & 3;    // 0..3 -> 64 cols

    float acc[4][8][4];
    #pragma unroll
    for (int mi = 0; mi < 4; mi++)
        #pragma unroll
        for (int ni = 0; ni < 8; ni++)
            #pragma unroll
            for (int r = 0; r < 4; r++) acc[mi][ni][r] = 0.0f;

    // loop-invariant pieces of the swizzled addresses
    const uint32_t aRow = (uint32_t)(warp_m * 64 + (lane & 15));      // + mi*16
    const uint32_t aKof = (uint32_t)((lane >> 4) * 16);               // + ks*32
    const uint32_t bRow = (uint32_t)(warp_n * 64 + (lane >> 2));      // + ni*8
    const uint32_t bKof = (uint32_t)((lane & 3) * 4);                 // + ks*32

    for (int kt = 0; kt < NKT; kt++) {
        const int s = kt & 3;
        mbar_wait(mb_full + 8 * s, (kt >> 2) & 1);
        const uint32_t sA = sb + TILES_OFF + s * STAGE_BYTES;
        const uint32_t sB = sA + A_TILE_BYTES;

        #pragma unroll
        for (int ks = 0; ks < 4; ks++) {
            uint32_t bfr[8][2];
            #pragma unroll
            for (int ni = 0; ni < 8; ni++) {
                const uint32_t off = (bRow + ni * 8) * 128 + ks * 32 + bKof;
                bfr[ni][0] = lds32(sB + swz128(off));
                bfr[ni][1] = lds32(sB + swz128(off + 16));
            }
            uint32_t afr[4][4];
            #pragma unroll
            for (int mi = 0; mi < 4; mi++) {
                const uint32_t off = (aRow + mi * 16) * 128 + ks * 32 + aKof;
                ldmatrix_x4(afr[mi][0], afr[mi][1], afr[mi][2], afr[mi][3],
                            sA + swz128(off));
            }
            #pragma unroll
            for (int mi = 0; mi < 4; mi++)
                #pragma unroll
                for (int ni = 0; ni < 8; ni++)
                    mma16816(acc[mi][ni], afr[mi], bfr[ni]);
        }
        mbar_arrive(mb_empty + 8 * s);
    }

    // epilogue: scale in fp32, float2 stores
    const int erow = mt * BM + warp_m * 64 + (lane >> 2);
    const int ecol = nt * BN + warp_n * 64 + 2 * (lane & 3);
    #pragma unroll
    for (int mi = 0; mi < 4; mi++) {
        #pragma unroll
        for (int ni = 0; ni < 8; ni++) {
            const int r0 = erow + mi * 16;
            const int cc = ecol + ni * 8;
            float2 v01 = make_float2(acc[mi][ni][0] * SCALE, acc[mi][ni][1] * SCALE);
            float2 v23 = make_float2(acc[mi][ni][2] * SCALE, acc[mi][ni][3] * SCALE);
            *reinterpret_cast<float2*>(C + (size_t)r0 * NDIM + cc)       = v01;
            *reinterpret_cast<float2*>(C + (size_t)(r0 + 8) * NDIM + cc) = v23;
        }
    }
}

// ---------------------------------------------------------------------------
// kernel_launch
// ---------------------------------------------------------------------------
extern "C" void kernel_launch(void* const* d_in, const int* in_sizes, int n_in,
                              void* d_out, int out_size) {
    const float* x = (const float*)d_in[0];
    const int*   w = (const int*)d_in[1];
    float* out = (float*)d_out;

    void *pW, *pA;
    cudaGetSymbolAddress(&pW, g_W);
    cudaGetSymbolAddress(&pA, g_A);

    k_prep<<<(W_CHUNKS + X_CHUNKS) / 256, 256>>>((const int4*)w, (const float4*)x,
                                                 (uint4*)pW, (uint4*)pA);

    cudaFuncSetAttribute(gemm_kernel, cudaFuncAttributeMaxDynamicSharedMemorySize,
                         SMEM_BYTES);
    dim3 grid(NDIM / BN, MDIM / BM);   // (16, 64)
    gemm_kernel<<<grid, 288, SMEM_BYTES>>>(out);
}